// round 10
// baseline (speedup 1.0000x reference)
#include <cuda_runtime.h>
#include <cuda_fp16.h>
#include <cstdint>

#define C_N 512
#define D_N 256
#define H_N 512
#define M_N 256
#define OH_N 512
#define E_N 261632

// ---------------------------------------------------------------------------
// Device scratch
// ---------------------------------------------------------------------------
__device__ __align__(16) __half g_Ph[4 * C_N * H_N];    // layer-1 projections, fp16
__device__ __align__(16) __half g_W2TH[2 * M_N * H_N];  // W2 transposed [t][n][k], fp16
__device__ __align__(16) float  g_agg[C_N * M_N];
__device__ __align__(16) float  g_h1[C_N * OH_N];
__device__ __align__(16) float  g_h2[C_N * OH_N];

// ---------------------------------------------------------------------------
// Helpers
// ---------------------------------------------------------------------------
__device__ __forceinline__ uint32_t smem_u32(const void* p) {
    uint32_t a;
    asm("{ .reg .u64 t; cvta.to.shared.u64 t, %1; cvt.u32.u64 %0, t; }" : "=r"(a) : "l"(p));
    return a;
}
__device__ __forceinline__ void cp16(uint32_t dst, const void* src) {
    asm volatile("cp.async.cg.shared.global [%0], [%1], 16;" :: "r"(dst), "l"(src));
}
#define CP_COMMIT() asm volatile("cp.async.commit_group;" ::: "memory")
#define CP_WAIT0()  asm volatile("cp.async.wait_group 0;" ::: "memory")

__device__ __forceinline__ void mma_f16(float* c, const uint32_t* a, const uint32_t* b) {
    asm volatile(
        "mma.sync.aligned.m16n8k16.row.col.f32.f16.f16.f32 "
        "{%0,%1,%2,%3}, {%4,%5,%6,%7}, {%8,%9}, {%0,%1,%2,%3};"
        : "+f"(c[0]), "+f"(c[1]), "+f"(c[2]), "+f"(c[3])
        : "r"(a[0]), "r"(a[1]), "r"(a[2]), "r"(a[3]), "r"(b[0]), "r"(b[1]));
}
__device__ __forceinline__ void ldmx4(uint32_t* r, uint32_t addr) {
    asm volatile("ldmatrix.sync.aligned.m8n8.x4.shared.b16 {%0,%1,%2,%3}, [%4];"
                 : "=r"(r[0]), "=r"(r[1]), "=r"(r[2]), "=r"(r[3]) : "r"(addr));
}

// ---------------------------------------------------------------------------
// fp32 GEMM body (64x64 tile, 256 thr) — proven R2..R9
// ---------------------------------------------------------------------------
__device__ __forceinline__ void gemm64_body(const float* __restrict__ A,
                                            const float* __restrict__ B,
                                            const float* __restrict__ bias,
                                            float* __restrict__ Cf,
                                            __half* __restrict__ Ch,
                                            int K, int N, int doRelu, int m0, int n0)
{
    __shared__ __align__(16) float sA[64][20];
    __shared__ __align__(16) float sB[16][64];

    int tid = threadIdx.x;
    int tx = tid & 15, ty = tid >> 4;
    float acc[4][4] = {};

    for (int k0 = 0; k0 < K; k0 += 16) {
        {
            int row = tid >> 2, cs = (tid & 3) * 4;
            float4 v = *(const float4*)(A + (m0 + row) * K + k0 + cs);
            *(float4*)&sA[row][cs] = v;
        }
        {
            int kk = tid >> 4, cs = (tid & 15) * 4;
            float4 v = *(const float4*)(B + (k0 + kk) * N + n0 + cs);
            *(float4*)&sB[kk][cs] = v;
        }
        __syncthreads();
        #pragma unroll
        for (int k = 0; k < 16; k++) {
            float a[4];
            #pragma unroll
            for (int i = 0; i < 4; i++) a[i] = sA[ty * 4 + i][k];
            float4 bv = *(const float4*)&sB[k][tx * 4];
            #pragma unroll
            for (int i = 0; i < 4; i++) {
                acc[i][0] = fmaf(a[i], bv.x, acc[i][0]);
                acc[i][1] = fmaf(a[i], bv.y, acc[i][1]);
                acc[i][2] = fmaf(a[i], bv.z, acc[i][2]);
                acc[i][3] = fmaf(a[i], bv.w, acc[i][3]);
            }
        }
        __syncthreads();
    }

    #pragma unroll
    for (int i = 0; i < 4; i++) {
        #pragma unroll
        for (int j = 0; j < 4; j++) {
            int n = n0 + tx * 4 + j;
            float v = acc[i][j] + (bias ? bias[n] : 0.0f);
            if (doRelu) v = fmaxf(v, 0.0f);
            if (Cf) Cf[(m0 + ty * 4 + i) * N + n] = v;
            else    Ch[(m0 + ty * 4 + i) * N + n] = __float2half_rn(v);
        }
    }
}

__global__ __launch_bounds__(256, 4)
void gemm64(const float* __restrict__ A, const float* __restrict__ B,
            const float* __restrict__ bias, float* __restrict__ Cmat,
            int K, int N, int doRelu)
{
    gemm64_body(A, B, bias, Cmat, nullptr, K, N, doRelu, blockIdx.y * 64, blockIdx.x * 64);
}

__global__ __launch_bounds__(256, 4)
void layer1_gemm_h(const float* __restrict__ inputs, const float* __restrict__ W1,
                   const float* __restrict__ b1)
{
    int z = blockIdx.z;
    const float* B = W1 + (size_t)z * D_N * H_N;
    const float* bias = ((z & 1) == 0) ? (b1 + (size_t)(z >> 1) * H_N) : nullptr;
    __half* outp = g_Ph + (size_t)z * C_N * H_N;
    gemm64_body(inputs, B, bias, nullptr, outp, D_N, H_N, 0, blockIdx.y * 64, blockIdx.x * 64);
}

__global__ void transpose_w2_h(const float* __restrict__ W2)
{
    __shared__ float tile[32][33];
    int t = blockIdx.z, k0 = blockIdx.x * 32, n0 = blockIdx.y * 32;
    const float* src = W2 + (size_t)t * H_N * M_N;
    __half* dst = g_W2TH + (size_t)t * M_N * H_N;
    #pragma unroll
    for (int i = 0; i < 4; i++)
        tile[threadIdx.y + i * 8][threadIdx.x] =
            src[(size_t)(k0 + threadIdx.y + i * 8) * M_N + n0 + threadIdx.x];
    __syncthreads();
    #pragma unroll
    for (int i = 0; i < 4; i++)
        dst[(size_t)(n0 + threadIdx.y + i * 8) * H_N + k0 + threadIdx.x] =
            __float2half_rn(tile[threadIdx.x][threadIdx.y + i * 8]);
}

__global__ void zero_agg_kernel()
{
    int i = blockIdx.x * blockDim.x + threadIdx.x;
    if (i < C_N * M_N) g_agg[i] = 0.0f;
}

// ---------------------------------------------------------------------------
// Edge kernel v6: CTA = 256 edges x 128 cols x ONE type. 512 thr, 16 warps
// (4m x 4n), warp tile 64x32 (4 m16 x 4 n8). ldmatrix.x4 fragments.
// KC=32 double-buffered. Direct atomicAdd scatter.
// ---------------------------------------------------------------------------
#define ET 256
#define ROWH 40
#define A_STAGE_H (ET * ROWH)      // 10240 halves (20KB)
#define B_STAGE_H (128 * ROWH)     // 5120 halves (10KB)
#define NKC (H_N / 32)             // 16
#define EDGE_SMEM ((2 * A_STAGE_H + 2 * B_STAGE_H) * 2)   // 61440 B

__global__ __launch_bounds__(512, 1)
void edge_mma_kernel(const float* __restrict__ b2, const float* __restrict__ rel,
                     const int* __restrict__ send, const int* __restrict__ rec)
{
    extern __shared__ __align__(16) __half dsm[];
    __half* sAbuf = dsm;                       // 2 stages [ET][ROWH]
    __half* sBbuf = dsm + 2 * A_STAGE_H;       // 2 stages [128][ROWH]
    __shared__ float s_relt[ET];
    __shared__ int   s_r[ET];
    __shared__ float s_b2[128];

    const int tid  = threadIdx.x;
    const int lane = tid & 31;
    const int warp = tid >> 5;
    const int mb  = (warp & 3) * 64;      // 64-edge strip
    const int nbw = (warp >> 2) * 32;     // 32-col strip
    const int e0 = blockIdx.x * ET;
    const int n0 = blockIdx.y * 128;
    const int t  = blockIdx.z;
    const int r4 = lane >> 2, c4 = lane & 3;

    if (tid < ET) {
        int p = e0 + tid;
        s_r[tid] = rec[p];
        s_relt[tid] = rel[(size_t)p * 2 + t];
    }
    if (tid < 128) s_b2[tid] = b2[t * M_N + n0 + tid];
    __syncthreads();

    // A staging: 2 threads per edge, 16 halves (2x16B) each
    const int le = tid >> 1;
    const int lq = tid & 1;
    const int sn = send[e0 + le];
    const int rn = s_r[le];

    // B staging: 4 threads per row, 8 halves each
    const int brow = tid >> 2;
    const int bq = tid & 3;
    const uint32_t sB_u32 = smem_u32(sBbuf);
    const uint32_t sA_u32 = smem_u32(sAbuf);

    const __half* PS = g_Ph + ((size_t)(t * 2 + 0) * C_N + sn) * H_N + lq * 16;
    const __half* PR = g_Ph + ((size_t)(t * 2 + 1) * C_N + rn) * H_N + lq * 16;
    const __half* WB = g_W2TH + ((size_t)t * M_N + n0 + brow) * H_N + bq * 8;

    // ldmatrix per-lane base addresses (bytes)
    const int lrA = lane & 15;
    const int khA = (lane >> 4) * 8;
    const int lrB = ((lane >> 4) & 1) * 8 + (lane & 7);
    const int khB = ((lane >> 3) & 1) * 8;
    uint32_t aBase[4], bBase[2];
    #pragma unroll
    for (int mt = 0; mt < 4; mt++)
        aBase[mt] = sA_u32 + (uint32_t)((mb + mt * 16 + lrA) * ROWH + khA) * 2u;
    #pragma unroll
    for (int p = 0; p < 2; p++)
        bBase[p] = sB_u32 + (uint32_t)((nbw + p * 16 + lrB) * ROWH + khB) * 2u;

    float acc[4][4][4];
    #pragma unroll
    for (int i = 0; i < 4; i++)
        #pragma unroll
        for (int j = 0; j < 4; j++)
            #pragma unroll
            for (int q = 0; q < 4; q++) acc[i][j][q] = 0.0f;

    uint4 pa0, pa1, pb0, pb1;
    const __half2 zero2 = __float2half2_rn(0.0f);

    // ---- prologue: chunk 0 -> buffer 0 ----
    {
        cp16(sB_u32 + (uint32_t)(brow * ROWH + bq * 8) * 2u, WB);
        CP_COMMIT();
        pa0 = *(const uint4*)PS;       pa1 = *(const uint4*)(PS + 8);
        pb0 = *(const uint4*)PR;       pb1 = *(const uint4*)(PR + 8);
        __half2 hh[8];
        const __half2* xa0 = (const __half2*)&pa0;
        const __half2* xa1 = (const __half2*)&pa1;
        const __half2* xb0 = (const __half2*)&pb0;
        const __half2* xb1 = (const __half2*)&pb1;
        #pragma unroll
        for (int i = 0; i < 4; i++) {
            hh[i]     = __hmax2(__hadd2(xa0[i], xb0[i]), zero2);
            hh[i + 4] = __hmax2(__hadd2(xa1[i], xb1[i]), zero2);
        }
        __half* dstA = sAbuf + le * ROWH + lq * 16;
        *(uint4*)dstA       = *(uint4*)&hh[0];
        *(uint4*)(dstA + 8) = *(uint4*)&hh[4];
        CP_WAIT0();
    }
    __syncthreads();

    #pragma unroll 1
    for (int kc = 0; kc < NKC; kc++) {
        const int cur = kc & 1, nxt = cur ^ 1;
        const bool more = (kc + 1 < NKC);
        if (more) {
            cp16(sB_u32 + (uint32_t)(nxt * B_STAGE_H + brow * ROWH + bq * 8) * 2u,
                 WB + (kc + 1) * 32);
            CP_COMMIT();
            pa0 = *(const uint4*)(PS + (kc + 1) * 32);
            pa1 = *(const uint4*)(PS + (kc + 1) * 32 + 8);
            pb0 = *(const uint4*)(PR + (kc + 1) * 32);
            pb1 = *(const uint4*)(PR + (kc + 1) * 32 + 8);
        }

        // ---- MMA on current buffers (ldmatrix fragments) ----
        const uint32_t aOff = (uint32_t)(cur * A_STAGE_H) * 2u;
        const uint32_t bOff = (uint32_t)(cur * B_STAGE_H) * 2u;
        #pragma unroll
        for (int ks = 0; ks < 2; ks++) {
            uint32_t af[4][4];
            #pragma unroll
            for (int mt = 0; mt < 4; mt++)
                ldmx4(af[mt], aBase[mt] + aOff + ks * 32);
            uint32_t bf[4][2];
            {
                uint32_t r[4];
                ldmx4(r, bBase[0] + bOff + ks * 32);
                bf[0][0] = r[0]; bf[0][1] = r[1]; bf[1][0] = r[2]; bf[1][1] = r[3];
                ldmx4(r, bBase[1] + bOff + ks * 32);
                bf[2][0] = r[0]; bf[2][1] = r[1]; bf[3][0] = r[2]; bf[3][1] = r[3];
            }
            #pragma unroll
            for (int nt = 0; nt < 4; nt++)
                #pragma unroll
                for (int mt = 0; mt < 4; mt++)
                    mma_f16(acc[mt][nt], af[mt], bf[nt]);
        }

        if (more) {
            __half2 hh[8];
            const __half2* xa0 = (const __half2*)&pa0;
            const __half2* xa1 = (const __half2*)&pa1;
            const __half2* xb0 = (const __half2*)&pb0;
            const __half2* xb1 = (const __half2*)&pb1;
            #pragma unroll
            for (int i = 0; i < 4; i++) {
                hh[i]     = __hmax2(__hadd2(xa0[i], xb0[i]), zero2);
                hh[i + 4] = __hmax2(__hadd2(xa1[i], xb1[i]), zero2);
            }
            __half* dstA = sAbuf + nxt * A_STAGE_H + le * ROWH + lq * 16;
            *(uint4*)dstA       = *(uint4*)&hh[0];
            *(uint4*)(dstA + 8) = *(uint4*)&hh[4];
            CP_WAIT0();
        }
        __syncthreads();
    }

    // ---- epilogue: weighted relu(acc + b2) -> direct atomic scatter ----
    #pragma unroll
    for (int mt = 0; mt < 4; mt++) {
        const int row0 = mb + mt * 16 + r4;
        const int row1 = row0 + 8;
        const float w0 = s_relt[row0];
        const float w1 = s_relt[row1];
        float* d0 = g_agg + (size_t)s_r[row0] * M_N + n0;
        float* d1 = g_agg + (size_t)s_r[row1] * M_N + n0;
        #pragma unroll
        for (int nt = 0; nt < 4; nt++) {
            const int col = nbw + nt * 8 + 2 * c4;
            const float bb0 = s_b2[col];
            const float bb1 = s_b2[col + 1];
            atomicAdd(d0 + col,     w0 * fmaxf(acc[mt][nt][0] + bb0, 0.0f));
            atomicAdd(d0 + col + 1, w0 * fmaxf(acc[mt][nt][1] + bb1, 0.0f));
            atomicAdd(d1 + col,     w1 * fmaxf(acc[mt][nt][2] + bb0, 0.0f));
            atomicAdd(d1 + col + 1, w1 * fmaxf(acc[mt][nt][3] + bb1, 0.0f));
        }
    }
}

// ---------------------------------------------------------------------------
// Launch
// ---------------------------------------------------------------------------
extern "C" void kernel_launch(void* const* d_in, const int* in_sizes, int n_in,
                              void* d_out, int out_size)
{
    const float* inputs = (const float*)d_in[0];
    const float* rel    = (const float*)d_in[1];
    const float* W1     = (const float*)d_in[2];
    const float* b1     = (const float*)d_in[3];
    const float* W2     = (const float*)d_in[4];
    const float* b2     = (const float*)d_in[5];
    const float* Wo1    = (const float*)d_in[6];
    const float* bo1    = (const float*)d_in[7];
    const float* Wo2    = (const float*)d_in[8];
    const float* bo2    = (const float*)d_in[9];
    const float* Wo3    = (const float*)d_in[10];
    const float* bo3    = (const float*)d_in[11];
    const int* send_idx = (const int*)d_in[12];
    const int* rec_idx  = (const int*)d_in[13];
    float* out = (float*)d_out;

    float *pAgg, *pH1, *pH2;
    cudaGetSymbolAddress((void**)&pAgg, g_agg);
    cudaGetSymbolAddress((void**)&pH1, g_h1);
    cudaGetSymbolAddress((void**)&pH2, g_h2);

    cudaFuncSetAttribute(edge_mma_kernel,
                         cudaFuncAttributeMaxDynamicSharedMemorySize, EDGE_SMEM);

    // Prep
    transpose_w2_h<<<dim3(H_N / 32, M_N / 32, 2), dim3(32, 8)>>>(W2);
    layer1_gemm_h<<<dim3(H_N / 64, C_N / 64, 4), 256>>>(inputs, W1, b1);
    zero_agg_kernel<<<(C_N * M_N + 255) / 256, 256>>>();

    // Main edge GEMM (type-split)
    edge_mma_kernel<<<dim3(E_N / ET, M_N / 128, 2), 512, EDGE_SMEM>>>(
        b2, rel, send_idx, rec_idx);

    // Output MLP (fp32)
    gemm64<<<dim3(OH_N / 64, C_N / 64), 256>>>(pAgg, Wo1, bo1, pH1, M_N, OH_N, 1);
    gemm64<<<dim3(OH_N / 64, C_N / 64), 256>>>(pH1, Wo2, bo2, pH2, OH_N, OH_N, 1);
    gemm64<<<dim3(D_N / 64, C_N / 64), 256>>>(pH2, Wo3, bo3, out, OH_N, D_N, 0);
}

// round 11
// speedup vs baseline: 1.1778x; 1.1778x over previous
#include <cuda_runtime.h>
#include <cuda_fp16.h>
#include <cstdint>

#define C_N 512
#define D_N 256
#define H_N 512
#define M_N 256
#define OH_N 512
#define E_N 261632

// ---------------------------------------------------------------------------
// Device scratch
// ---------------------------------------------------------------------------
__device__ __align__(16) __half g_Ph[4 * C_N * H_N];    // layer-1 projections, fp16
__device__ __align__(16) __half g_W2TH[2 * M_N * H_N];  // W2 transposed [t][n][k], fp16
__device__ __align__(16) float  g_agg[C_N * M_N];
__device__ __align__(16) float  g_h1[C_N * OH_N];
__device__ __align__(16) float  g_h2[C_N * OH_N];
__device__ int g_hist[512];
__device__ int g_cursor[512];
__device__ int g_perm[E_N];

// ---------------------------------------------------------------------------
// Helpers
// ---------------------------------------------------------------------------
__device__ __forceinline__ uint32_t smem_u32(const void* p) {
    uint32_t a;
    asm("{ .reg .u64 t; cvta.to.shared.u64 t, %1; cvt.u32.u64 %0, t; }" : "=r"(a) : "l"(p));
    return a;
}
__device__ __forceinline__ void cp16(uint32_t dst, const void* src) {
    asm volatile("cp.async.cg.shared.global [%0], [%1], 16;" :: "r"(dst), "l"(src));
}
#define CP_COMMIT() asm volatile("cp.async.commit_group;" ::: "memory")
#define CP_WAIT0()  asm volatile("cp.async.wait_group 0;" ::: "memory")

__device__ __forceinline__ void mma_f16(float* c, const uint32_t* a, const uint32_t* b) {
    asm volatile(
        "mma.sync.aligned.m16n8k16.row.col.f32.f16.f16.f32 "
        "{%0,%1,%2,%3}, {%4,%5,%6,%7}, {%8,%9}, {%0,%1,%2,%3};"
        : "+f"(c[0]), "+f"(c[1]), "+f"(c[2]), "+f"(c[3])
        : "r"(a[0]), "r"(a[1]), "r"(a[2]), "r"(a[3]), "r"(b[0]), "r"(b[1]));
}
__device__ __forceinline__ void ldmx4(uint32_t* r, uint32_t addr) {
    asm volatile("ldmatrix.sync.aligned.m8n8.x4.shared.b16 {%0,%1,%2,%3}, [%4];"
                 : "=r"(r[0]), "=r"(r[1]), "=r"(r[2]), "=r"(r[3]) : "r"(addr));
}

// ---------------------------------------------------------------------------
// fp32 GEMM body (64x64 tile, 256 thr) — proven R2..R10
// ---------------------------------------------------------------------------
__device__ __forceinline__ void gemm64_body(const float* __restrict__ A,
                                            const float* __restrict__ B,
                                            const float* __restrict__ bias,
                                            float* __restrict__ Cf,
                                            __half* __restrict__ Ch,
                                            int K, int N, int doRelu, int m0, int n0)
{
    __shared__ __align__(16) float sA[64][20];
    __shared__ __align__(16) float sB[16][64];

    int tid = threadIdx.x;
    int tx = tid & 15, ty = tid >> 4;
    float acc[4][4] = {};

    for (int k0 = 0; k0 < K; k0 += 16) {
        {
            int row = tid >> 2, cs = (tid & 3) * 4;
            float4 v = *(const float4*)(A + (m0 + row) * K + k0 + cs);
            *(float4*)&sA[row][cs] = v;
        }
        {
            int kk = tid >> 4, cs = (tid & 15) * 4;
            float4 v = *(const float4*)(B + (k0 + kk) * N + n0 + cs);
            *(float4*)&sB[kk][cs] = v;
        }
        __syncthreads();
        #pragma unroll
        for (int k = 0; k < 16; k++) {
            float a[4];
            #pragma unroll
            for (int i = 0; i < 4; i++) a[i] = sA[ty * 4 + i][k];
            float4 bv = *(const float4*)&sB[k][tx * 4];
            #pragma unroll
            for (int i = 0; i < 4; i++) {
                acc[i][0] = fmaf(a[i], bv.x, acc[i][0]);
                acc[i][1] = fmaf(a[i], bv.y, acc[i][1]);
                acc[i][2] = fmaf(a[i], bv.z, acc[i][2]);
                acc[i][3] = fmaf(a[i], bv.w, acc[i][3]);
            }
        }
        __syncthreads();
    }

    #pragma unroll
    for (int i = 0; i < 4; i++) {
        #pragma unroll
        for (int j = 0; j < 4; j++) {
            int n = n0 + tx * 4 + j;
            float v = acc[i][j] + (bias ? bias[n] : 0.0f);
            if (doRelu) v = fmaxf(v, 0.0f);
            if (Cf) Cf[(m0 + ty * 4 + i) * N + n] = v;
            else    Ch[(m0 + ty * 4 + i) * N + n] = __float2half_rn(v);
        }
    }
}

__global__ __launch_bounds__(256, 4)
void gemm64(const float* __restrict__ A, const float* __restrict__ B,
            const float* __restrict__ bias, float* __restrict__ Cmat,
            int K, int N, int doRelu)
{
    gemm64_body(A, B, bias, Cmat, nullptr, K, N, doRelu, blockIdx.y * 64, blockIdx.x * 64);
}

__global__ __launch_bounds__(256, 4)
void layer1_gemm_h(const float* __restrict__ inputs, const float* __restrict__ W1,
                   const float* __restrict__ b1)
{
    int z = blockIdx.z;
    const float* B = W1 + (size_t)z * D_N * H_N;
    const float* bias = ((z & 1) == 0) ? (b1 + (size_t)(z >> 1) * H_N) : nullptr;
    __half* outp = g_Ph + (size_t)z * C_N * H_N;
    gemm64_body(inputs, B, bias, nullptr, outp, D_N, H_N, 0, blockIdx.y * 64, blockIdx.x * 64);
}

__global__ void transpose_w2_h(const float* __restrict__ W2)
{
    __shared__ float tile[32][33];
    int t = blockIdx.z, k0 = blockIdx.x * 32, n0 = blockIdx.y * 32;
    const float* src = W2 + (size_t)t * H_N * M_N;
    __half* dst = g_W2TH + (size_t)t * M_N * H_N;
    #pragma unroll
    for (int i = 0; i < 4; i++)
        tile[threadIdx.y + i * 8][threadIdx.x] =
            src[(size_t)(k0 + threadIdx.y + i * 8) * M_N + n0 + threadIdx.x];
    __syncthreads();
    #pragma unroll
    for (int i = 0; i < 4; i++)
        dst[(size_t)(n0 + threadIdx.y + i * 8) * H_N + k0 + threadIdx.x] =
            __float2half_rn(tile[threadIdx.x][threadIdx.y + i * 8]);
}

// ---------------------------------------------------------------------------
// Counting sort of edges by receiver (proven R7)
// ---------------------------------------------------------------------------
__global__ void zero_kernel()
{
    int i = blockIdx.x * blockDim.x + threadIdx.x;
    if (i < C_N * M_N) g_agg[i] = 0.0f;
    if (i < 512) g_hist[i] = 0;
}

__global__ __launch_bounds__(512)
void hist_kernel(const int* __restrict__ rec)
{
    __shared__ int h[512];
    int tid = threadIdx.x;
    h[tid] = 0;
    __syncthreads();
    for (int e = blockIdx.x * 512 + tid; e < E_N; e += gridDim.x * 512)
        atomicAdd(&h[rec[e]], 1);
    __syncthreads();
    atomicAdd(&g_hist[tid], h[tid]);
}

__global__ __launch_bounds__(512)
void scan_kernel()
{
    __shared__ int tmp[2][512];
    int tid = threadIdx.x;
    int v = g_hist[tid];
    tmp[0][tid] = v;
    __syncthreads();
    int src = 0;
    for (int off = 1; off < 512; off <<= 1) {
        int val = tmp[src][tid];
        if (tid >= off) val += tmp[src][tid - off];
        tmp[src ^ 1][tid] = val;
        src ^= 1;
        __syncthreads();
    }
    g_cursor[tid] = tmp[src][tid] - v;   // exclusive prefix
}

__global__ __launch_bounds__(256)
void mkperm_kernel(const int* __restrict__ rec)
{
    for (int e = blockIdx.x * blockDim.x + threadIdx.x; e < E_N;
         e += gridDim.x * blockDim.x) {
        int c = rec[e];
        int pos = atomicAdd(&g_cursor[c], 1);
        g_perm[pos] = e;
    }
}

// ---------------------------------------------------------------------------
// Edge kernel v7: CTA = 256 SORTED edges x 128 cols x ONE type. 512 thr,
// 16 warps (4m x 4n), warp tile 64x32 (4 m16 x 4 n8), ldmatrix fragments,
// KC=32 double-buffered. Epilogue: in-register cross-lane (shfl) reduction
// over the warp's 64 sorted rows -> 32 atomic lanes/warp (64x fewer).
// ---------------------------------------------------------------------------
#define ET 256
#define ROWH 40
#define A_STAGE_H (ET * ROWH)      // 10240 halves (20KB)
#define B_STAGE_H (128 * ROWH)     // 5120 halves (10KB)
#define NKC (H_N / 32)             // 16
#define EDGE_SMEM ((2 * A_STAGE_H + 2 * B_STAGE_H) * 2)   // 61440 B

__global__ __launch_bounds__(512, 1)
void edge_mma_kernel(const float* __restrict__ b2, const float* __restrict__ rel,
                     const int* __restrict__ send, const int* __restrict__ rec)
{
    extern __shared__ __align__(16) __half dsm[];
    __half* sAbuf = dsm;                       // 2 stages [ET][ROWH]
    __half* sBbuf = dsm + 2 * A_STAGE_H;       // 2 stages [128][ROWH]
    __shared__ float s_relt[ET];
    __shared__ int   s_r[ET];
    __shared__ int   s_p[ET];
    __shared__ float s_b2[128];

    const int tid  = threadIdx.x;
    const int lane = tid & 31;
    const int warp = tid >> 5;
    const int mb  = (warp & 3) * 64;      // 64-edge strip
    const int nbw = (warp >> 2) * 32;     // 32-col strip
    const int e0 = blockIdx.x * ET;
    const int n0 = blockIdx.y * 128;
    const int t  = blockIdx.z;
    const int r4 = lane >> 2, c4 = lane & 3;

    if (tid < ET) {
        int p = g_perm[e0 + tid];
        s_p[tid] = p;
        s_r[tid] = rec[p];
        s_relt[tid] = rel[(size_t)p * 2 + t];
    }
    if (tid < 128) s_b2[tid] = b2[t * M_N + n0 + tid];
    __syncthreads();

    // A staging: 2 threads per edge, 16 halves (2x16B) each
    const int le = tid >> 1;
    const int lq = tid & 1;
    const int sn = send[s_p[le]];
    const int rn = s_r[le];

    // B staging: 4 threads per row, 8 halves each
    const int brow = tid >> 2;
    const int bq = tid & 3;
    const uint32_t sB_u32 = smem_u32(sBbuf);
    const uint32_t sA_u32 = smem_u32(sAbuf);

    const __half* PS = g_Ph + ((size_t)(t * 2 + 0) * C_N + sn) * H_N + lq * 16;
    const __half* PR = g_Ph + ((size_t)(t * 2 + 1) * C_N + rn) * H_N + lq * 16;
    const __half* WB = g_W2TH + ((size_t)t * M_N + n0 + brow) * H_N + bq * 8;

    // ldmatrix per-lane base addresses (bytes)
    const int lrA = lane & 15;
    const int khA = (lane >> 4) * 8;
    const int lrB = ((lane >> 4) & 1) * 8 + (lane & 7);
    const int khB = ((lane >> 3) & 1) * 8;
    uint32_t aBase[4], bBase[2];
    #pragma unroll
    for (int mt = 0; mt < 4; mt++)
        aBase[mt] = sA_u32 + (uint32_t)((mb + mt * 16 + lrA) * ROWH + khA) * 2u;
    #pragma unroll
    for (int p = 0; p < 2; p++)
        bBase[p] = sB_u32 + (uint32_t)((nbw + p * 16 + lrB) * ROWH + khB) * 2u;

    float acc[4][4][4];
    #pragma unroll
    for (int i = 0; i < 4; i++)
        #pragma unroll
        for (int j = 0; j < 4; j++)
            #pragma unroll
            for (int q = 0; q < 4; q++) acc[i][j][q] = 0.0f;

    uint4 pa0, pa1, pb0, pb1;
    const __half2 zero2 = __float2half2_rn(0.0f);

    // ---- prologue: chunk 0 -> buffer 0 ----
    {
        cp16(sB_u32 + (uint32_t)(brow * ROWH + bq * 8) * 2u, WB);
        CP_COMMIT();
        pa0 = *(const uint4*)PS;       pa1 = *(const uint4*)(PS + 8);
        pb0 = *(const uint4*)PR;       pb1 = *(const uint4*)(PR + 8);
        __half2 hh[8];
        const __half2* xa0 = (const __half2*)&pa0;
        const __half2* xa1 = (const __half2*)&pa1;
        const __half2* xb0 = (const __half2*)&pb0;
        const __half2* xb1 = (const __half2*)&pb1;
        #pragma unroll
        for (int i = 0; i < 4; i++) {
            hh[i]     = __hmax2(__hadd2(xa0[i], xb0[i]), zero2);
            hh[i + 4] = __hmax2(__hadd2(xa1[i], xb1[i]), zero2);
        }
        __half* dstA = sAbuf + le * ROWH + lq * 16;
        *(uint4*)dstA       = *(uint4*)&hh[0];
        *(uint4*)(dstA + 8) = *(uint4*)&hh[4];
        CP_WAIT0();
    }
    __syncthreads();

    #pragma unroll 1
    for (int kc = 0; kc < NKC; kc++) {
        const int cur = kc & 1, nxt = cur ^ 1;
        const bool more = (kc + 1 < NKC);
        if (more) {
            cp16(sB_u32 + (uint32_t)(nxt * B_STAGE_H + brow * ROWH + bq * 8) * 2u,
                 WB + (kc + 1) * 32);
            CP_COMMIT();
            pa0 = *(const uint4*)(PS + (kc + 1) * 32);
            pa1 = *(const uint4*)(PS + (kc + 1) * 32 + 8);
            pb0 = *(const uint4*)(PR + (kc + 1) * 32);
            pb1 = *(const uint4*)(PR + (kc + 1) * 32 + 8);
        }

        // ---- MMA on current buffers (ldmatrix fragments) ----
        const uint32_t aOff = (uint32_t)(cur * A_STAGE_H) * 2u;
        const uint32_t bOff = (uint32_t)(cur * B_STAGE_H) * 2u;
        #pragma unroll
        for (int ks = 0; ks < 2; ks++) {
            uint32_t af[4][4];
            #pragma unroll
            for (int mt = 0; mt < 4; mt++)
                ldmx4(af[mt], aBase[mt] + aOff + ks * 32);
            uint32_t bf[4][2];
            {
                uint32_t r[4];
                ldmx4(r, bBase[0] + bOff + ks * 32);
                bf[0][0] = r[0]; bf[0][1] = r[1]; bf[1][0] = r[2]; bf[1][1] = r[3];
                ldmx4(r, bBase[1] + bOff + ks * 32);
                bf[2][0] = r[0]; bf[2][1] = r[1]; bf[3][0] = r[2]; bf[3][1] = r[3];
            }
            #pragma unroll
            for (int nt = 0; nt < 4; nt++)
                #pragma unroll
                for (int mt = 0; mt < 4; mt++)
                    mma_f16(acc[mt][nt], af[mt], bf[nt]);
        }

        if (more) {
            __half2 hh[8];
            const __half2* xa0 = (const __half2*)&pa0;
            const __half2* xa1 = (const __half2*)&pa1;
            const __half2* xb0 = (const __half2*)&pb0;
            const __half2* xb1 = (const __half2*)&pb1;
            #pragma unroll
            for (int i = 0; i < 4; i++) {
                hh[i]     = __hmax2(__hadd2(xa0[i], xb0[i]), zero2);
                hh[i + 4] = __hmax2(__hadd2(xa1[i], xb1[i]), zero2);
            }
            __half* dstA = sAbuf + nxt * A_STAGE_H + le * ROWH + lq * 16;
            *(uint4*)dstA       = *(uint4*)&hh[0];
            *(uint4*)(dstA + 8) = *(uint4*)&hh[4];
            CP_WAIT0();
        }
        __syncthreads();
    }

    // ---- epilogue ----
    const bool uniform = (s_r[mb] == s_r[mb + 63]);
    if (uniform) {
        // In-register reduction over the warp's 64 rows (single receiver).
        float cs[4][2];
        #pragma unroll
        for (int nt = 0; nt < 4; nt++) { cs[nt][0] = 0.0f; cs[nt][1] = 0.0f; }
        #pragma unroll
        for (int mt = 0; mt < 4; mt++) {
            const int row0 = mb + mt * 16 + r4;
            const float w0 = s_relt[row0];
            const float w1 = s_relt[row0 + 8];
            #pragma unroll
            for (int nt = 0; nt < 4; nt++) {
                const int col = nbw + nt * 8 + 2 * c4;
                const float bb0 = s_b2[col];
                const float bb1 = s_b2[col + 1];
                cs[nt][0] += w0 * fmaxf(acc[mt][nt][0] + bb0, 0.0f)
                           + w1 * fmaxf(acc[mt][nt][2] + bb0, 0.0f);
                cs[nt][1] += w0 * fmaxf(acc[mt][nt][1] + bb1, 0.0f)
                           + w1 * fmaxf(acc[mt][nt][3] + bb1, 0.0f);
            }
        }
        // butterfly over r4 (lanes differing by 4/8/16)
        #pragma unroll
        for (int off = 4; off < 32; off <<= 1)
            #pragma unroll
            for (int nt = 0; nt < 4; nt++) {
                cs[nt][0] += __shfl_xor_sync(0xFFFFFFFFu, cs[nt][0], off);
                cs[nt][1] += __shfl_xor_sync(0xFFFFFFFFu, cs[nt][1], off);
            }
        if (lane < 4) {
            float* dst = g_agg + (size_t)s_r[mb] * M_N + n0;
            #pragma unroll
            for (int nt = 0; nt < 4; nt++) {
                const int col = nbw + nt * 8 + 2 * c4;
                atomicAdd(dst + col,     cs[nt][0]);
                atomicAdd(dst + col + 1, cs[nt][1]);
            }
        }
    } else {
        // boundary strip: per-row atomics (rare with sorted edges)
        #pragma unroll
        for (int mt = 0; mt < 4; mt++) {
            const int row0 = mb + mt * 16 + r4;
            const int row1 = row0 + 8;
            const float w0 = s_relt[row0];
            const float w1 = s_relt[row1];
            float* d0 = g_agg + (size_t)s_r[row0] * M_N + n0;
            float* d1 = g_agg + (size_t)s_r[row1] * M_N + n0;
            #pragma unroll
            for (int nt = 0; nt < 4; nt++) {
                const int col = nbw + nt * 8 + 2 * c4;
                const float bb0 = s_b2[col];
                const float bb1 = s_b2[col + 1];
                atomicAdd(d0 + col,     w0 * fmaxf(acc[mt][nt][0] + bb0, 0.0f));
                atomicAdd(d0 + col + 1, w0 * fmaxf(acc[mt][nt][1] + bb1, 0.0f));
                atomicAdd(d1 + col,     w1 * fmaxf(acc[mt][nt][2] + bb0, 0.0f));
                atomicAdd(d1 + col + 1, w1 * fmaxf(acc[mt][nt][3] + bb1, 0.0f));
            }
        }
    }
}

// ---------------------------------------------------------------------------
// Launch
// ---------------------------------------------------------------------------
extern "C" void kernel_launch(void* const* d_in, const int* in_sizes, int n_in,
                              void* d_out, int out_size)
{
    const float* inputs = (const float*)d_in[0];
    const float* rel    = (const float*)d_in[1];
    const float* W1     = (const float*)d_in[2];
    const float* b1     = (const float*)d_in[3];
    const float* W2     = (const float*)d_in[4];
    const float* b2     = (const float*)d_in[5];
    const float* Wo1    = (const float*)d_in[6];
    const float* bo1    = (const float*)d_in[7];
    const float* Wo2    = (const float*)d_in[8];
    const float* bo2    = (const float*)d_in[9];
    const float* Wo3    = (const float*)d_in[10];
    const float* bo3    = (const float*)d_in[11];
    const int* send_idx = (const int*)d_in[12];
    const int* rec_idx  = (const int*)d_in[13];
    float* out = (float*)d_out;

    float *pAgg, *pH1, *pH2;
    cudaGetSymbolAddress((void**)&pAgg, g_agg);
    cudaGetSymbolAddress((void**)&pH1, g_h1);
    cudaGetSymbolAddress((void**)&pH2, g_h2);

    cudaFuncSetAttribute(edge_mma_kernel,
                         cudaFuncAttributeMaxDynamicSharedMemorySize, EDGE_SMEM);

    // Prep: weights + projections + receiver sort
    transpose_w2_h<<<dim3(H_N / 32, M_N / 32, 2), dim3(32, 8)>>>(W2);
    layer1_gemm_h<<<dim3(H_N / 64, C_N / 64, 4), 256>>>(inputs, W1, b1);
    zero_kernel<<<(C_N * M_N + 255) / 256, 256>>>();
    hist_kernel<<<128, 512>>>(rec_idx);
    scan_kernel<<<1, 512>>>();
    mkperm_kernel<<<256, 256>>>(rec_idx);

    // Main edge GEMM (type-split, sorted) + reduced scatter
    edge_mma_kernel<<<dim3(E_N / ET, M_N / 128, 2), 512, EDGE_SMEM>>>(
        b2, rel, send_idx, rec_idx);

    // Output MLP (fp32)
    gemm64<<<dim3(OH_N / 64, C_N / 64), 256>>>(pAgg, Wo1, bo1, pH1, M_N, OH_N, 1);
    gemm64<<<dim3(OH_N / 64, C_N / 64), 256>>>(pH1, Wo2, bo2, pH2, OH_N, OH_N, 1);
    gemm64<<<dim3(D_N / 64, C_N / 64), 256>>>(pH2, Wo3, bo3, out, OH_N, D_N, 0);
}